// round 1
// baseline (speedup 1.0000x reference)
#include <cuda_runtime.h>
#include <math.h>

#define NTOK   (16 * 4096)   // 65536 tokens
#define D_IN   512
#define D_K    256
#define MSLOTS 64

// Scratch for encoded activations (64 MB). __device__ global = allowed scratch.
__device__ float g_encoded[(size_t)NTOK * D_K];

// ---------------------------------------------------------------------------
// SGEMM: C[M,N] = act(A[M,K] @ B[N,K]^T + bias[N])
// BM=BN=128, BK=8, 256 threads, 8x8 per-thread tile.
// All dims assumed divisible by tile sizes (they are: M=65536, N in {256,512},
// K in {512,256}).
// ---------------------------------------------------------------------------
template <bool DO_TANH>
__global__ __launch_bounds__(256, 2)
void sgemm_bt_kernel(const float* __restrict__ A,
                     const float* __restrict__ B,
                     const float* __restrict__ bias,
                     float* __restrict__ C,
                     int M, int N, int K)
{
    constexpr int BM = 128, BN = 128, BK = 8;
    __shared__ float As[BK][BM];
    __shared__ float Bs[BK][BN];

    const int tid = threadIdx.x;
    const int m0 = blockIdx.y * BM;
    const int n0 = blockIdx.x * BN;

    // load indexing: 256 threads, each loads one float4 of A and one of B
    const int ld_row = tid >> 1;        // 0..127
    const int ld_col = (tid & 1) * 4;   // 0 or 4
    const float* Ap = A + (size_t)(m0 + ld_row) * K + ld_col;
    const float* Bp = B + (size_t)(n0 + ld_row) * K + ld_col;

    const int tx = tid & 15;   // 0..15 -> 8 cols each
    const int ty = tid >> 4;   // 0..15 -> 8 rows each

    float acc[8][8];
#pragma unroll
    for (int i = 0; i < 8; i++)
#pragma unroll
        for (int j = 0; j < 8; j++) acc[i][j] = 0.f;

    for (int k0 = 0; k0 < K; k0 += BK) {
        float4 av = *(const float4*)(Ap + k0);
        float4 bv = *(const float4*)(Bp + k0);
        As[ld_col + 0][ld_row] = av.x;
        As[ld_col + 1][ld_row] = av.y;
        As[ld_col + 2][ld_row] = av.z;
        As[ld_col + 3][ld_row] = av.w;
        Bs[ld_col + 0][ld_row] = bv.x;
        Bs[ld_col + 1][ld_row] = bv.y;
        Bs[ld_col + 2][ld_row] = bv.z;
        Bs[ld_col + 3][ld_row] = bv.w;
        __syncthreads();

#pragma unroll
        for (int kk = 0; kk < BK; kk++) {
            float a[8], b[8];
            *(float4*)&a[0] = *(const float4*)&As[kk][ty * 8];
            *(float4*)&a[4] = *(const float4*)&As[kk][ty * 8 + 4];
            *(float4*)&b[0] = *(const float4*)&Bs[kk][tx * 8];
            *(float4*)&b[4] = *(const float4*)&Bs[kk][tx * 8 + 4];
#pragma unroll
            for (int i = 0; i < 8; i++)
#pragma unroll
                for (int j = 0; j < 8; j++)
                    acc[i][j] = fmaf(a[i], b[j], acc[i][j]);
        }
        __syncthreads();
    }

    float bfr[8];
#pragma unroll
    for (int j = 0; j < 8; j++) bfr[j] = bias[n0 + tx * 8 + j];

#pragma unroll
    for (int i = 0; i < 8; i++) {
        const size_t row = (size_t)(m0 + ty * 8 + i);
        float* Cp = C + row * N + n0 + tx * 8;
        float v[8];
#pragma unroll
        for (int j = 0; j < 8; j++) {
            float x = acc[i][j] + bfr[j];
            v[j] = DO_TANH ? tanhf(x) : x;
        }
        *(float4*)(Cp + 0) = make_float4(v[0], v[1], v[2], v[3]);
        *(float4*)(Cp + 4) = make_float4(v[4], v[5], v[6], v[7]);
    }
}

// ---------------------------------------------------------------------------
// Attention kernel: per token t
//   logits[m] = dot(encoded[t], mem[m]) / 16     (m = 0..63)
//   att = softmax(logits)
//   memory[k] = sum_m att[m] * mem[m][k]         (k = 0..255)
// One warp per token. mem bank resident in padded SMEM (row pitch 257 to
// kill bank conflicts on column-strided reads). Block = 8 warps, loops over
// 64 tokens to amortize the mem-bank load from L2.
// ---------------------------------------------------------------------------
__global__ __launch_bounds__(256)
void attn_kernel(const float* __restrict__ encoded,
                 const float* __restrict__ mem,
                 float* __restrict__ att_out,
                 float* __restrict__ mem_out)
{
    extern __shared__ float sm[];
    float* mem_s = sm;                       // 64 * 257
    float* e_s   = sm + 64 * 257;            // 8 warps * 256
    float* att_s = e_s + 8 * 256;            // 8 warps * 64

    const int tid = threadIdx.x;
    const int w = tid >> 5;
    const int l = tid & 31;

    // stage memory bank into smem (padded rows)
    for (int idx = tid; idx < MSLOTS * D_K; idx += 256) {
        int r = idx >> 8;         // idx / 256
        int c = idx & 255;
        mem_s[r * 257 + c] = mem[idx];
    }
    __syncthreads();

    float* ew = e_s + w * 256;
    float* aw = att_s + w * 64;
    const int tbase = blockIdx.x * 64;

    for (int it = 0; it < 8; it++) {
        const int t = tbase + it * 8 + w;

        // stage this token's encoded vector
        const float* ep = encoded + (size_t)t * D_K;
#pragma unroll
        for (int j = 0; j < 8; j++) ew[l + 32 * j] = ep[l + 32 * j];
        __syncwarp();

        // logits for slots m = l and m = l + 32
        float s0 = 0.f, s1 = 0.f;
        const float* r0 = mem_s + l * 257;
        const float* r1 = mem_s + (l + 32) * 257;
#pragma unroll 8
        for (int k = 0; k < 256; k++) {
            float e = ew[k];
            s0 = fmaf(r0[k], e, s0);
            s1 = fmaf(r1[k], e, s1);
        }
        s0 *= 0.0625f;   // / sqrt(256)
        s1 *= 0.0625f;

        // warp softmax over 64 values (2 per lane)
        float mx = fmaxf(s0, s1);
#pragma unroll
        for (int o = 16; o > 0; o >>= 1)
            mx = fmaxf(mx, __shfl_xor_sync(0xffffffffu, mx, o));
        float p0 = expf(s0 - mx);
        float p1 = expf(s1 - mx);
        float sum = p0 + p1;
#pragma unroll
        for (int o = 16; o > 0; o >>= 1)
            sum += __shfl_xor_sync(0xffffffffu, sum, o);
        float inv = 1.f / sum;
        float a0 = p0 * inv;
        float a1 = p1 * inv;

        att_out[(size_t)t * MSLOTS + l]      = a0;
        att_out[(size_t)t * MSLOTS + l + 32] = a1;
        aw[l] = a0;
        aw[l + 32] = a1;
        __syncwarp();

        // memory read: memory[k] = sum_m att[m] * mem[m][k]
        float accv[8];
#pragma unroll
        for (int j = 0; j < 8; j++) accv[j] = 0.f;
#pragma unroll 4
        for (int m = 0; m < MSLOTS; m++) {
            float a = aw[m];
            const float* mr = mem_s + m * 257 + l;
#pragma unroll
            for (int j = 0; j < 8; j++)
                accv[j] = fmaf(mr[32 * j], a, accv[j]);
        }
        float* mo = mem_out + (size_t)t * D_K;
#pragma unroll
        for (int j = 0; j < 8; j++) mo[l + 32 * j] = accv[j];
        __syncwarp();
    }
}

// ---------------------------------------------------------------------------
// launch
// ---------------------------------------------------------------------------
extern "C" void kernel_launch(void* const* d_in, const int* in_sizes, int n_in,
                              void* d_out, int out_size)
{
    const float* seq   = (const float*)d_in[0];  // [B,S,512]
    const float* enc_w = (const float*)d_in[1];  // [256,512]
    const float* enc_b = (const float*)d_in[2];  // [256]
    const float* mem   = (const float*)d_in[3];  // [64,256]
    const float* dec_w = (const float*)d_in[4];  // [512,256]
    const float* dec_b = (const float*)d_in[5];  // [512]

    const int ntok = in_sizes[0] / D_IN;         // 65536

    float* out   = (float*)d_out;
    float* recon = out;                                       // [ntok,512]
    float* att   = out + (size_t)ntok * D_IN;                 // [ntok,64]
    float* memo  = att + (size_t)ntok * MSLOTS;               // [ntok,256]

    float* enc_g = nullptr;
    cudaGetSymbolAddress((void**)&enc_g, g_encoded);

    // K1: encoded = tanh(seq @ enc_w^T + enc_b)
    {
        dim3 grid(D_K / 128, ntok / 128);
        sgemm_bt_kernel<true><<<grid, 256>>>(seq, enc_w, enc_b, enc_g,
                                             ntok, D_K, D_IN);
    }

    // K2: attention + memory read
    {
        const int smem_bytes = (64 * 257 + 8 * 256 + 8 * 64) * (int)sizeof(float);
        cudaFuncSetAttribute(attn_kernel,
                             cudaFuncAttributeMaxDynamicSharedMemorySize,
                             smem_bytes);
        attn_kernel<<<ntok / 64, 256, smem_bytes>>>(enc_g, mem, att, memo);
    }

    // K3: reconstruction = memory @ dec_w^T + dec_b
    {
        dim3 grid(D_IN / 128, ntok / 128);
        sgemm_bt_kernel<false><<<grid, 256>>>(memo, dec_w, dec_b, recon,
                                              ntok, D_IN, D_K);
    }
}

// round 5
// speedup vs baseline: 2.9751x; 2.9751x over previous
#include <cuda_runtime.h>
#include <cuda_bf16.h>
#include <stdint.h>
#include <math.h>

#define NTOK   (16 * 4096)   // 65536 tokens
#define D_IN   512
#define D_K    256
#define MSLOTS 64

// ---------------------------------------------------------------------------
// Scratch (bf16 split-pair representations + logits)
// ---------------------------------------------------------------------------
__device__ __align__(256) __nv_bfloat16 g_Sh[(size_t)NTOK * D_IN];
__device__ __align__(256) __nv_bfloat16 g_Sl[(size_t)NTOK * D_IN];
__device__ __align__(256) __nv_bfloat16 g_Eh[(size_t)NTOK * D_K];
__device__ __align__(256) __nv_bfloat16 g_El[(size_t)NTOK * D_K];
__device__ __align__(256) float         g_logits[(size_t)NTOK * MSLOTS];
__device__ __align__(256) __nv_bfloat16 g_ATh[(size_t)NTOK * MSLOTS];
__device__ __align__(256) __nv_bfloat16 g_ATl[(size_t)NTOK * MSLOTS];
__device__ __align__(256) __nv_bfloat16 g_Mh[(size_t)NTOK * D_K];
__device__ __align__(256) __nv_bfloat16 g_Ml[(size_t)NTOK * D_K];
__device__ __align__(256) __nv_bfloat16 g_EWh[D_K * D_IN], g_EWl[D_K * D_IN];
__device__ __align__(256) __nv_bfloat16 g_MEMh[MSLOTS * D_K], g_MEMl[MSLOTS * D_K];
__device__ __align__(256) __nv_bfloat16 g_MTh[D_K * MSLOTS], g_MTl[D_K * MSLOTS];
__device__ __align__(256) __nv_bfloat16 g_DWh[D_IN * D_K], g_DWl[D_IN * D_K];

// ---------------------------------------------------------------------------
// PTX helpers (all plain-sm_103-legal: cp.async, ldmatrix, mma.sync)
// ---------------------------------------------------------------------------
__device__ __forceinline__ uint32_t smem_u32(const void* p) {
    uint32_t a;
    asm("{ .reg .u64 t; cvta.to.shared.u64 t, %1; cvt.u32.u64 %0, t; }"
        : "=r"(a) : "l"(p));
    return a;
}

__device__ __forceinline__ void cp16(uint32_t dst, const void* src) {
    asm volatile("cp.async.cg.shared.global [%0], [%1], 16;"
                 :: "r"(dst), "l"(src));
}
__device__ __forceinline__ void cp_commit() {
    asm volatile("cp.async.commit_group;");
}
__device__ __forceinline__ void cp_wait0() {
    asm volatile("cp.async.wait_group 0;" ::: "memory");
}

#define LDSM4(r0, r1, r2, r3, addr)                                            \
    asm volatile("ldmatrix.sync.aligned.m8n8.x4.shared.b16 {%0,%1,%2,%3}, [%4];" \
                 : "=r"(r0), "=r"(r1), "=r"(r2), "=r"(r3) : "r"(addr))

#define LDSM2(r0, r1, addr)                                                    \
    asm volatile("ldmatrix.sync.aligned.m8n8.x2.shared.b16 {%0,%1}, [%2];"     \
                 : "=r"(r0), "=r"(r1) : "r"(addr))

#define MMA16816(c, a, b)                                                      \
    asm volatile(                                                              \
        "mma.sync.aligned.m16n8k16.row.col.f32.bf16.bf16.f32 "                 \
        "{%0,%1,%2,%3},{%4,%5,%6,%7},{%8,%9},{%0,%1,%2,%3};"                   \
        : "+f"((c)[0]), "+f"((c)[1]), "+f"((c)[2]), "+f"((c)[3])               \
        : "r"((a)[0]), "r"((a)[1]), "r"((a)[2]), "r"((a)[3]),                  \
          "r"((b)[0]), "r"((b)[1]))

// ---------------------------------------------------------------------------
// Split-bf16 GEMM via mma.sync:  C[M, Ntotal] = epi(A @ B^T + bias)
//   A = Ah + Al  [M, K]   bf16-pair, row-major (K contiguous)
//   B = Bh + Bl  [Ntotal, K] bf16-pair, row-major (K contiguous)
// 3 accumulation passes per k-step: Ah*Bh + Ah*Bl + Al*Bh (fp32 accum).
// CTA tile 128 x NT, BK=32, 256 threads, warps 2(m) x 4(n).
// EPI: 0 = +bias, tanh, write bf16 pair (Ch, Cl)
//      1 = identity, write fp32 (Cf)
//      2 = identity, write fp32 (Cf) AND bf16 pair (Ch, Cl)
//      3 = +bias, write fp32 (Cf)
// ---------------------------------------------------------------------------
template <int NT, int EPI>
__global__ __launch_bounds__(256)
void mma_gemm(const __nv_bfloat16* __restrict__ Ah, const __nv_bfloat16* __restrict__ Al,
              const __nv_bfloat16* __restrict__ Bh, const __nv_bfloat16* __restrict__ Bl,
              const float* __restrict__ bias,
              float* __restrict__ Cf,
              __nv_bfloat16* __restrict__ Ch, __nv_bfloat16* __restrict__ Cl,
              int Ntotal, int K)
{
    constexpr int NW  = NT / 32;           // n8-tiles per warp (4 or 2)
    constexpr int NWC = NT / 4;            // n-cols per warp (32 or 16)
    constexpr int A_BYTES = 128 * 40 * 2;  // 10240 (pitch 40 bf16 = 80 B)
    constexpr int B_BYTES = NT * 40 * 2;
    constexpr int OFF_AH = 0, OFF_AL = A_BYTES;
    constexpr int OFF_BH = 2 * A_BYTES, OFF_BL = 2 * A_BYTES + B_BYTES;
    constexpr int STAGE = 2 * A_BYTES + 2 * B_BYTES;

    extern __shared__ char smem[];
    const uint32_t sb = smem_u32(smem);

    const int tid  = threadIdx.x;
    const int lane = tid & 31;
    const int wid  = tid >> 5;
    const int wm   = wid & 1;              // 0..1
    const int wn   = wid >> 1;             // 0..3
    const int m0   = blockIdx.y * 128;
    const int n0   = blockIdx.x * NT;

    float c[4][NW][4];
#pragma unroll
    for (int mi = 0; mi < 4; mi++)
#pragma unroll
        for (int ni = 0; ni < NW; ni++)
#pragma unroll
            for (int j = 0; j < 4; j++) c[mi][ni][j] = 0.f;

    const int nch = K >> 5;

    // ---- loader (cp.async, 16B granules; pad bytes of each 80B row unused)
    auto load_chunk = [&](int ch) {
        const uint32_t st = sb + (uint32_t)((ch & 1) * STAGE);
        const int kc = ch * 32;
#pragma unroll
        for (int i = 0; i < 2; i++) {
            int e = tid + i * 256;          // 0..511
            int r = e >> 2, g = e & 3;
            uint32_t d = st + (uint32_t)(r * 80 + g * 16);
            size_t go = (size_t)(m0 + r) * K + kc + g * 8;
            cp16(d + OFF_AH, Ah + go);
            cp16(d + OFF_AL, Al + go);
        }
#pragma unroll
        for (int i = 0; i < NT / 64; i++) {
            int e = tid + i * 256;
            int r = e >> 2, g = e & 3;
            uint32_t d = st + (uint32_t)(r * 80 + g * 16);
            size_t go = (size_t)(n0 + r) * K + kc + g * 8;
            cp16(d + OFF_BH, Bh + go);
            cp16(d + OFF_BL, Bl + go);
        }
        cp_commit();
    };

    load_chunk(0);

    // ldmatrix base addresses (per lane)
    const uint32_t aRow = (uint32_t)((wm * 64 + (lane & 15)) * 80 + (lane >> 4) * 16);
    const uint32_t bRow = (uint32_t)((wn * NWC + (lane & 7)) * 80 + ((lane >> 3) & 1) * 16);

    for (int ch = 0; ch < nch; ch++) {
        cp_wait0();
        __syncthreads();
        if (ch + 1 < nch) load_chunk(ch + 1);

        const uint32_t st = sb + (uint32_t)((ch & 1) * STAGE);
#pragma unroll
        for (int kk = 0; kk < 2; kk++) {      // two k16 steps in BK=32
            uint32_t ah[4][4], al[4][4], bh[NW][2], bl[NW][2];
#pragma unroll
            for (int mi = 0; mi < 4; mi++) {
                uint32_t ad = st + aRow + (uint32_t)(mi * 1280 + kk * 32);
                LDSM4(ah[mi][0], ah[mi][1], ah[mi][2], ah[mi][3], ad + OFF_AH);
                LDSM4(al[mi][0], al[mi][1], al[mi][2], al[mi][3], ad + OFF_AL);
            }
#pragma unroll
            for (int ni = 0; ni < NW; ni++) {
                uint32_t bd = st + bRow + (uint32_t)(ni * 640 + kk * 32);
                LDSM2(bh[ni][0], bh[ni][1], bd + OFF_BH);
                LDSM2(bl[ni][0], bl[ni][1], bd + OFF_BL);
            }
#pragma unroll
            for (int mi = 0; mi < 4; mi++)
#pragma unroll
                for (int ni = 0; ni < NW; ni++) {
                    MMA16816(c[mi][ni], ah[mi], bh[ni]);
                    MMA16816(c[mi][ni], ah[mi], bl[ni]);
                    MMA16816(c[mi][ni], al[mi], bh[ni]);
                }
        }
        __syncthreads();
    }

    // ---- epilogue
    const int r_in  = lane >> 2;
    const int cpair = (lane & 3) * 2;
#pragma unroll
    for (int mi = 0; mi < 4; mi++) {
        const int rg = m0 + wm * 64 + mi * 16 + r_in;
#pragma unroll
        for (int ni = 0; ni < NW; ni++) {
            const int cg = n0 + wn * NWC + ni * 8 + cpair;
            float v0 = c[mi][ni][0], v1 = c[mi][ni][1];
            float v2 = c[mi][ni][2], v3 = c[mi][ni][3];
            if (EPI == 0 || EPI == 3) {
                float b0 = bias[cg], b1 = bias[cg + 1];
                v0 += b0; v1 += b1; v2 += b0; v3 += b1;
            }
            if (EPI == 0) {
                v0 = tanhf(v0); v1 = tanhf(v1); v2 = tanhf(v2); v3 = tanhf(v3);
            }
            if (EPI == 1 || EPI == 2 || EPI == 3) {
                float2* p0 = (float2*)(Cf + (size_t)rg * Ntotal + cg);
                float2* p1 = (float2*)(Cf + (size_t)(rg + 8) * Ntotal + cg);
                *p0 = make_float2(v0, v1);
                *p1 = make_float2(v2, v3);
            }
            if (EPI == 0 || EPI == 2) {
                __nv_bfloat16 h0 = __float2bfloat16(v0);
                __nv_bfloat16 h1 = __float2bfloat16(v1);
                __nv_bfloat16 h2 = __float2bfloat16(v2);
                __nv_bfloat16 h3 = __float2bfloat16(v3);
                __nv_bfloat162 ph0; ph0.x = h0; ph0.y = h1;
                __nv_bfloat162 ph1; ph1.x = h2; ph1.y = h3;
                __nv_bfloat162 pl0;
                pl0.x = __float2bfloat16(v0 - __bfloat162float(h0));
                pl0.y = __float2bfloat16(v1 - __bfloat162float(h1));
                __nv_bfloat162 pl1;
                pl1.x = __float2bfloat16(v2 - __bfloat162float(h2));
                pl1.y = __float2bfloat16(v3 - __bfloat162float(h3));
                *(__nv_bfloat162*)(Ch + (size_t)rg * Ntotal + cg)       = ph0;
                *(__nv_bfloat162*)(Ch + (size_t)(rg + 8) * Ntotal + cg) = ph1;
                *(__nv_bfloat162*)(Cl + (size_t)rg * Ntotal + cg)       = pl0;
                *(__nv_bfloat162*)(Cl + (size_t)(rg + 8) * Ntotal + cg) = pl1;
            }
        }
    }
}

// ---------------------------------------------------------------------------
// Softmax over 64 memory slots; writes fp32 attention (d_out) + bf16 pair
// ---------------------------------------------------------------------------
__global__ __launch_bounds__(256)
void softmax_kernel(const float* __restrict__ logits,
                    float* __restrict__ att,
                    __nv_bfloat16* __restrict__ ah,
                    __nv_bfloat16* __restrict__ al)
{
    const int wid = threadIdx.x >> 5, lid = threadIdx.x & 31;
    const size_t t = (size_t)blockIdx.x * 8 + wid;
    const float* lp = logits + t * MSLOTS;

    float s0 = lp[lid] * 0.0625f;        // / sqrt(256)
    float s1 = lp[lid + 32] * 0.0625f;
    float mx = fmaxf(s0, s1);
#pragma unroll
    for (int o = 16; o > 0; o >>= 1)
        mx = fmaxf(mx, __shfl_xor_sync(0xffffffffu, mx, o));
    float p0 = expf(s0 - mx);
    float p1 = expf(s1 - mx);
    float sum = p0 + p1;
#pragma unroll
    for (int o = 16; o > 0; o >>= 1)
        sum += __shfl_xor_sync(0xffffffffu, sum, o);
    float inv = 1.f / sum;
    float a0 = p0 * inv, a1 = p1 * inv;

    att[t * MSLOTS + lid]      = a0;
    att[t * MSLOTS + lid + 32] = a1;

    __nv_bfloat16 h0 = __float2bfloat16(a0);
    __nv_bfloat16 h1 = __float2bfloat16(a1);
    ah[t * MSLOTS + lid]      = h0;
    ah[t * MSLOTS + lid + 32] = h1;
    al[t * MSLOTS + lid]      = __float2bfloat16(a0 - __bfloat162float(h0));
    al[t * MSLOTS + lid + 32] = __float2bfloat16(a1 - __bfloat162float(h1));
}

// ---------------------------------------------------------------------------
// fp32 -> bf16 (hi, lo) split conversions
// ---------------------------------------------------------------------------
__global__ void cvt_pair4(const float4* __restrict__ x,
                          uint32_t* __restrict__ h, uint32_t* __restrict__ l, int n4)
{
    int i = blockIdx.x * blockDim.x + threadIdx.x;
    if (i >= n4) return;
    float4 v = x[i];
    float vv[4] = {v.x, v.y, v.z, v.w};
    __nv_bfloat16 hh[4], ll[4];
#pragma unroll
    for (int j = 0; j < 4; j++) {
        hh[j] = __float2bfloat16(vv[j]);
        ll[j] = __float2bfloat16(vv[j] - __bfloat162float(hh[j]));
    }
    __nv_bfloat162 p0h; p0h.x = hh[0]; p0h.y = hh[1];
    __nv_bfloat162 p1h; p1h.x = hh[2]; p1h.y = hh[3];
    __nv_bfloat162 p0l; p0l.x = ll[0]; p0l.y = ll[1];
    __nv_bfloat162 p1l; p1l.x = ll[2]; p1l.y = ll[3];
    h[2*i]   = *(uint32_t*)&p0h;
    h[2*i+1] = *(uint32_t*)&p1h;
    l[2*i]   = *(uint32_t*)&p0l;
    l[2*i+1] = *(uint32_t*)&p1l;
}

// transpose convert: in [rows][cols] -> out [cols][rows]
__global__ void cvt_pairT(const float* __restrict__ x,
                          __nv_bfloat16* __restrict__ h, __nv_bfloat16* __restrict__ l,
                          int rows, int cols)
{
    int i = blockIdx.x * blockDim.x + threadIdx.x;
    if (i >= rows * cols) return;
    int r = i / cols, cidx = i % cols;
    float v = x[i];
    __nv_bfloat16 hi = __float2bfloat16(v);
    h[(size_t)cidx * rows + r] = hi;
    l[(size_t)cidx * rows + r] = __float2bfloat16(v - __bfloat162float(hi));
}

// ---------------------------------------------------------------------------
// launch
// ---------------------------------------------------------------------------
extern "C" void kernel_launch(void* const* d_in, const int* in_sizes, int n_in,
                              void* d_out, int out_size)
{
    const float* seq   = (const float*)d_in[0];  // [NTOK,512]
    const float* enc_w = (const float*)d_in[1];  // [256,512]
    const float* enc_b = (const float*)d_in[2];  // [256]
    const float* mem   = (const float*)d_in[3];  // [64,256]
    const float* dec_w = (const float*)d_in[4];  // [512,256]
    const float* dec_b = (const float*)d_in[5];  // [512]

    float* out   = (float*)d_out;
    float* recon = out;                                 // [NTOK,512]
    float* att   = out + (size_t)NTOK * D_IN;           // [NTOK,64]
    float* memo  = att + (size_t)NTOK * MSLOTS;         // [NTOK,256]

    __nv_bfloat16 *Sh, *Sl, *Eh, *El, *ATh, *ATl, *Mh, *Ml;
    __nv_bfloat16 *EWh, *EWl, *MEMh, *MEMl, *MTh, *MTl, *DWh, *DWl;
    float* LG;
    cudaGetSymbolAddress((void**)&Sh, g_Sh);   cudaGetSymbolAddress((void**)&Sl, g_Sl);
    cudaGetSymbolAddress((void**)&Eh, g_Eh);   cudaGetSymbolAddress((void**)&El, g_El);
    cudaGetSymbolAddress((void**)&ATh, g_ATh); cudaGetSymbolAddress((void**)&ATl, g_ATl);
    cudaGetSymbolAddress((void**)&Mh, g_Mh);   cudaGetSymbolAddress((void**)&Ml, g_Ml);
    cudaGetSymbolAddress((void**)&EWh, g_EWh); cudaGetSymbolAddress((void**)&EWl, g_EWl);
    cudaGetSymbolAddress((void**)&MEMh, g_MEMh); cudaGetSymbolAddress((void**)&MEMl, g_MEMl);
    cudaGetSymbolAddress((void**)&MTh, g_MTh); cudaGetSymbolAddress((void**)&MTl, g_MTl);
    cudaGetSymbolAddress((void**)&DWh, g_DWh); cudaGetSymbolAddress((void**)&DWl, g_DWl);
    cudaGetSymbolAddress((void**)&LG, g_logits);

    // dynamic smem sizes: 2 stages * (A hi+lo + B hi+lo)
    const int SM128 = 2 * (2 * 10240 + 2 * 128 * 80);   // 81920
    const int SM64  = 2 * (2 * 10240 + 2 * 64 * 80);    // 61440
    cudaFuncSetAttribute(mma_gemm<128, 0>, cudaFuncAttributeMaxDynamicSharedMemorySize, SM128);
    cudaFuncSetAttribute(mma_gemm<64, 1>,  cudaFuncAttributeMaxDynamicSharedMemorySize, SM64);
    cudaFuncSetAttribute(mma_gemm<128, 2>, cudaFuncAttributeMaxDynamicSharedMemorySize, SM128);
    cudaFuncSetAttribute(mma_gemm<128, 3>, cudaFuncAttributeMaxDynamicSharedMemorySize, SM128);

    // conversions
    {
        int n4 = NTOK * D_IN / 4;
        cvt_pair4<<<(n4 + 255) / 256, 256>>>((const float4*)seq, (uint32_t*)Sh, (uint32_t*)Sl, n4);
        n4 = D_K * D_IN / 4;
        cvt_pair4<<<(n4 + 255) / 256, 256>>>((const float4*)enc_w, (uint32_t*)EWh, (uint32_t*)EWl, n4);
        n4 = MSLOTS * D_K / 4;
        cvt_pair4<<<(n4 + 255) / 256, 256>>>((const float4*)mem, (uint32_t*)MEMh, (uint32_t*)MEMl, n4);
        cvt_pairT<<<(MSLOTS * D_K + 255) / 256, 256>>>(mem, MTh, MTl, MSLOTS, D_K);
        n4 = D_IN * D_K / 4;
        cvt_pair4<<<(n4 + 255) / 256, 256>>>((const float4*)dec_w, (uint32_t*)DWh, (uint32_t*)DWl, n4);
    }

    // 1) encoded = tanh(seq @ enc_w^T + enc_b)  -> bf16 pair
    {
        dim3 grid(D_K / 128, NTOK / 128);
        mma_gemm<128, 0><<<grid, 256, SM128>>>(Sh, Sl, EWh, EWl, enc_b,
                                               nullptr, Eh, El, D_K, D_IN);
    }
    // 2) logits = encoded @ mem^T  -> fp32
    {
        dim3 grid(1, NTOK / 128);
        mma_gemm<64, 1><<<grid, 256, SM64>>>(Eh, El, MEMh, MEMl, nullptr,
                                             LG, nullptr, nullptr, MSLOTS, D_K);
    }
    // 3) softmax -> att (d_out) + bf16 pair
    softmax_kernel<<<NTOK / 8, 256>>>(LG, att, ATh, ATl);

    // 4) memory = att @ mem  -> fp32 (d_out) + bf16 pair
    {
        dim3 grid(D_K / 128, NTOK / 128);
        mma_gemm<128, 2><<<grid, 256, SM128>>>(ATh, ATl, MTh, MTl, nullptr,
                                               memo, Mh, Ml, D_K, MSLOTS);
    }
    // 5) recon = memory @ dec_w^T + dec_b -> fp32 (d_out)
    {
        dim3 grid(D_IN / 128, NTOK / 128);
        mma_gemm<128, 3><<<grid, 256, SM128>>>(Mh, Ml, DWh, DWl, dec_b,
                                               recon, nullptr, nullptr, D_IN, D_K);
    }
}

// round 6
// speedup vs baseline: 5.1673x; 1.7369x over previous
#include <cuda_runtime.h>
#include <cuda_fp16.h>
#include <stdint.h>
#include <math.h>

#define NTOK   (16 * 4096)   // 65536 tokens
#define D_IN   512
#define D_K    256
#define MSLOTS 64

// ---------------------------------------------------------------------------
// Scratch (fp16 representations + logits)
// ---------------------------------------------------------------------------
__device__ __align__(256) __half g_S[(size_t)NTOK * D_IN];    // seq fp16
__device__ __align__(256) __half g_E[(size_t)NTOK * D_K];     // encoded fp16
__device__ __align__(256) float  g_logits[(size_t)NTOK * MSLOTS];
__device__ __align__(256) __half g_AT[(size_t)NTOK * MSLOTS]; // attention fp16
__device__ __align__(256) __half g_M[(size_t)NTOK * D_K];     // memory-read fp16
__device__ __align__(256) __half g_EW[D_K * D_IN];            // enc_w fp16
__device__ __align__(256) __half g_MEM[MSLOTS * D_K];         // mem fp16
__device__ __align__(256) __half g_MT[D_K * MSLOTS];          // mem^T fp16
__device__ __align__(256) __half g_DW[D_IN * D_K];            // dec_w fp16

// ---------------------------------------------------------------------------
// PTX helpers (plain-sm_103-legal: cp.async, ldmatrix, mma.sync)
// ---------------------------------------------------------------------------
__device__ __forceinline__ uint32_t smem_u32(const void* p) {
    uint32_t a;
    asm("{ .reg .u64 t; cvta.to.shared.u64 t, %1; cvt.u32.u64 %0, t; }"
        : "=r"(a) : "l"(p));
    return a;
}

__device__ __forceinline__ void cp16(uint32_t dst, const void* src) {
    asm volatile("cp.async.cg.shared.global [%0], [%1], 16;"
                 :: "r"(dst), "l"(src));
}
__device__ __forceinline__ void cp_commit() {
    asm volatile("cp.async.commit_group;");
}
__device__ __forceinline__ void cp_wait0() {
    asm volatile("cp.async.wait_group 0;" ::: "memory");
}

#define LDSM4(r0, r1, r2, r3, addr)                                            \
    asm volatile("ldmatrix.sync.aligned.m8n8.x4.shared.b16 {%0,%1,%2,%3}, [%4];" \
                 : "=r"(r0), "=r"(r1), "=r"(r2), "=r"(r3) : "r"(addr))

#define LDSM2(r0, r1, addr)                                                    \
    asm volatile("ldmatrix.sync.aligned.m8n8.x2.shared.b16 {%0,%1}, [%2];"     \
                 : "=r"(r0), "=r"(r1) : "r"(addr))

#define MMA16816(c, a, b)                                                      \
    asm volatile(                                                              \
        "mma.sync.aligned.m16n8k16.row.col.f32.f16.f16.f32 "                   \
        "{%0,%1,%2,%3},{%4,%5,%6,%7},{%8,%9},{%0,%1,%2,%3};"                   \
        : "+f"((c)[0]), "+f"((c)[1]), "+f"((c)[2]), "+f"((c)[3])               \
        : "r"((a)[0]), "r"((a)[1]), "r"((a)[2]), "r"((a)[3]),                  \
          "r"((b)[0]), "r"((b)[1]))

// ---------------------------------------------------------------------------
// fp16 GEMM via mma.sync:  C[M, Ntotal] = epi(A @ B^T + bias)
//   A [M, K] fp16 row-major, B [Ntotal, K] fp16 row-major. fp32 accumulate.
// CTA tile 128 x NT, BK=32, 256 threads, warps 2(m) x 4(n).
// EPI: 0 = +bias, tanh, write fp16 (Ch)
//      1 = identity, write fp32 (Cf)
//      2 = identity, write fp32 (Cf) AND fp16 (Ch)
//      3 = +bias, write fp32 (Cf)
// ---------------------------------------------------------------------------
template <int NT, int EPI>
__global__ __launch_bounds__(256)
void mma_gemm(const __half* __restrict__ A,
              const __half* __restrict__ B,
              const float* __restrict__ bias,
              float* __restrict__ Cf,
              __half* __restrict__ Ch,
              int Ntotal, int K)
{
    constexpr int NW  = NT / 32;           // n8-tiles per warp (4 or 2)
    constexpr int NWC = NT / 4;            // n-cols per warp (32 or 16)
    constexpr int A_BYTES = 128 * 40 * 2;  // 10240 (pitch 40 halfs = 80 B)
    constexpr int B_BYTES = NT * 40 * 2;
    constexpr int OFF_A = 0, OFF_B = A_BYTES;
    constexpr int STAGE = A_BYTES + B_BYTES;

    extern __shared__ char smem[];
    const uint32_t sb = smem_u32(smem);

    const int tid  = threadIdx.x;
    const int lane = tid & 31;
    const int wid  = tid >> 5;
    const int wm   = wid & 1;              // 0..1
    const int wn   = wid >> 1;             // 0..3
    const int m0   = blockIdx.y * 128;
    const int n0   = blockIdx.x * NT;

    float c[4][NW][4];
#pragma unroll
    for (int mi = 0; mi < 4; mi++)
#pragma unroll
        for (int ni = 0; ni < NW; ni++)
#pragma unroll
            for (int j = 0; j < 4; j++) c[mi][ni][j] = 0.f;

    const int nch = K >> 5;

    // ---- loader (cp.async, 16B granules; pad bytes of each 80B row unused)
    auto load_chunk = [&](int ch) {
        const uint32_t st = sb + (uint32_t)((ch & 1) * STAGE);
        const int kc = ch * 32;
#pragma unroll
        for (int i = 0; i < 2; i++) {
            int e = tid + i * 256;          // 0..511 (128 rows x 4 granules)
            int r = e >> 2, g = e & 3;
            uint32_t d = st + (uint32_t)(r * 80 + g * 16);
            size_t go = (size_t)(m0 + r) * K + kc + g * 8;
            cp16(d + OFF_A, A + go);
        }
#pragma unroll
        for (int i = 0; i < NT / 64; i++) {
            int e = tid + i * 256;
            int r = e >> 2, g = e & 3;
            uint32_t d = st + (uint32_t)(r * 80 + g * 16);
            size_t go = (size_t)(n0 + r) * K + kc + g * 8;
            cp16(d + OFF_B, B + go);
        }
        cp_commit();
    };

    load_chunk(0);

    // ldmatrix base addresses (per lane)
    const uint32_t aRow = (uint32_t)((wm * 64 + (lane & 15)) * 80 + (lane >> 4) * 16);
    const uint32_t bRow = (uint32_t)((wn * NWC + (lane & 7)) * 80 + ((lane >> 3) & 1) * 16);

    for (int ch = 0; ch < nch; ch++) {
        cp_wait0();
        __syncthreads();
        if (ch + 1 < nch) load_chunk(ch + 1);

        const uint32_t st = sb + (uint32_t)((ch & 1) * STAGE);
#pragma unroll
        for (int kk = 0; kk < 2; kk++) {      // two k16 steps in BK=32
            uint32_t a[4][4], b[NW][2];
#pragma unroll
            for (int mi = 0; mi < 4; mi++) {
                uint32_t ad = st + aRow + (uint32_t)(mi * 1280 + kk * 32);
                LDSM4(a[mi][0], a[mi][1], a[mi][2], a[mi][3], ad + OFF_A);
            }
#pragma unroll
            for (int ni = 0; ni < NW; ni++) {
                uint32_t bd = st + bRow + (uint32_t)(ni * 640 + kk * 32);
                LDSM2(b[ni][0], b[ni][1], bd + OFF_B);
            }
#pragma unroll
            for (int mi = 0; mi < 4; mi++)
#pragma unroll
                for (int ni = 0; ni < NW; ni++)
                    MMA16816(c[mi][ni], a[mi], b[ni]);
        }
        __syncthreads();
    }

    // ---- epilogue
    const int r_in  = lane >> 2;
    const int cpair = (lane & 3) * 2;
#pragma unroll
    for (int mi = 0; mi < 4; mi++) {
        const int rg = m0 + wm * 64 + mi * 16 + r_in;
#pragma unroll
        for (int ni = 0; ni < NW; ni++) {
            const int cg = n0 + wn * NWC + ni * 8 + cpair;
            float v0 = c[mi][ni][0], v1 = c[mi][ni][1];
            float v2 = c[mi][ni][2], v3 = c[mi][ni][3];
            if (EPI == 0 || EPI == 3) {
                float b0 = bias[cg], b1 = bias[cg + 1];
                v0 += b0; v1 += b1; v2 += b0; v3 += b1;
            }
            if (EPI == 0) {
                v0 = tanhf(v0); v1 = tanhf(v1); v2 = tanhf(v2); v3 = tanhf(v3);
            }
            if (EPI == 1 || EPI == 2 || EPI == 3) {
                float2* p0 = (float2*)(Cf + (size_t)rg * Ntotal + cg);
                float2* p1 = (float2*)(Cf + (size_t)(rg + 8) * Ntotal + cg);
                *p0 = make_float2(v0, v1);
                *p1 = make_float2(v2, v3);
            }
            if (EPI == 0 || EPI == 2) {
                __half2 h0 = __floats2half2_rn(v0, v1);
                __half2 h1 = __floats2half2_rn(v2, v3);
                *(__half2*)(Ch + (size_t)rg * Ntotal + cg)       = h0;
                *(__half2*)(Ch + (size_t)(rg + 8) * Ntotal + cg) = h1;
            }
        }
    }
}

// ---------------------------------------------------------------------------
// Softmax over 64 memory slots; writes fp32 attention (d_out) + fp16
// ---------------------------------------------------------------------------
__global__ __launch_bounds__(256)
void softmax_kernel(const float* __restrict__ logits,
                    float* __restrict__ att,
                    __half* __restrict__ ah)
{
    const int wid = threadIdx.x >> 5, lid = threadIdx.x & 31;
    const size_t t = (size_t)blockIdx.x * 8 + wid;
    const float* lp = logits + t * MSLOTS;

    float s0 = lp[lid] * 0.0625f;        // / sqrt(256)
    float s1 = lp[lid + 32] * 0.0625f;
    float mx = fmaxf(s0, s1);
#pragma unroll
    for (int o = 16; o > 0; o >>= 1)
        mx = fmaxf(mx, __shfl_xor_sync(0xffffffffu, mx, o));
    float p0 = expf(s0 - mx);
    float p1 = expf(s1 - mx);
    float sum = p0 + p1;
#pragma unroll
    for (int o = 16; o > 0; o >>= 1)
        sum += __shfl_xor_sync(0xffffffffu, sum, o);
    float inv = 1.f / sum;
    float a0 = p0 * inv, a1 = p1 * inv;

    att[t * MSLOTS + lid]      = a0;
    att[t * MSLOTS + lid + 32] = a1;
    ah[t * MSLOTS + lid]       = __float2half_rn(a0);
    ah[t * MSLOTS + lid + 32]  = __float2half_rn(a1);
}

// ---------------------------------------------------------------------------
// fp32 -> fp16 conversions
// ---------------------------------------------------------------------------
__global__ void cvt_half4(const float4* __restrict__ x,
                          __half2* __restrict__ h, int n4)
{
    int i = blockIdx.x * blockDim.x + threadIdx.x;
    if (i >= n4) return;
    float4 v = x[i];
    h[2*i]   = __floats2half2_rn(v.x, v.y);
    h[2*i+1] = __floats2half2_rn(v.z, v.w);
}

// transpose convert: in [rows][cols] -> out [cols][rows]
__global__ void cvt_halfT(const float* __restrict__ x,
                          __half* __restrict__ h, int rows, int cols)
{
    int i = blockIdx.x * blockDim.x + threadIdx.x;
    if (i >= rows * cols) return;
    int r = i / cols, cidx = i % cols;
    h[(size_t)cidx * rows + r] = __float2half_rn(x[i]);
}

// ---------------------------------------------------------------------------
// launch
// ---------------------------------------------------------------------------
extern "C" void kernel_launch(void* const* d_in, const int* in_sizes, int n_in,
                              void* d_out, int out_size)
{
    const float* seq   = (const float*)d_in[0];  // [NTOK,512]
    const float* enc_w = (const float*)d_in[1];  // [256,512]
    const float* enc_b = (const float*)d_in[2];  // [256]
    const float* mem   = (const float*)d_in[3];  // [64,256]
    const float* dec_w = (const float*)d_in[4];  // [512,256]
    const float* dec_b = (const float*)d_in[5];  // [512]

    float* out   = (float*)d_out;
    float* recon = out;                                 // [NTOK,512]
    float* att   = out + (size_t)NTOK * D_IN;           // [NTOK,64]
    float* memo  = att + (size_t)NTOK * MSLOTS;         // [NTOK,256]

    __half *S, *E, *AT, *M, *EW, *MEM, *MT, *DW;
    float* LG;
    cudaGetSymbolAddress((void**)&S, g_S);
    cudaGetSymbolAddress((void**)&E, g_E);
    cudaGetSymbolAddress((void**)&AT, g_AT);
    cudaGetSymbolAddress((void**)&M, g_M);
    cudaGetSymbolAddress((void**)&EW, g_EW);
    cudaGetSymbolAddress((void**)&MEM, g_MEM);
    cudaGetSymbolAddress((void**)&MT, g_MT);
    cudaGetSymbolAddress((void**)&DW, g_DW);
    cudaGetSymbolAddress((void**)&LG, g_logits);

    // dynamic smem: 2 stages * (A + B)
    const int SM128 = 2 * (10240 + 128 * 80);   // 40960
    const int SM64  = 2 * (10240 + 64 * 80);    // 30720
    cudaFuncSetAttribute(mma_gemm<128, 0>, cudaFuncAttributeMaxDynamicSharedMemorySize, SM128);
    cudaFuncSetAttribute(mma_gemm<64, 1>,  cudaFuncAttributeMaxDynamicSharedMemorySize, SM64);
    cudaFuncSetAttribute(mma_gemm<128, 2>, cudaFuncAttributeMaxDynamicSharedMemorySize, SM128);
    cudaFuncSetAttribute(mma_gemm<128, 3>, cudaFuncAttributeMaxDynamicSharedMemorySize, SM128);

    // conversions
    {
        int n4 = NTOK * D_IN / 4;
        cvt_half4<<<(n4 + 255) / 256, 256>>>((const float4*)seq, (__half2*)S, n4);
        n4 = D_K * D_IN / 4;
        cvt_half4<<<(n4 + 255) / 256, 256>>>((const float4*)enc_w, (__half2*)EW, n4);
        n4 = MSLOTS * D_K / 4;
        cvt_half4<<<(n4 + 255) / 256, 256>>>((const float4*)mem, (__half2*)MEM, n4);
        cvt_halfT<<<(MSLOTS * D_K + 255) / 256, 256>>>(mem, MT, MSLOTS, D_K);
        n4 = D_IN * D_K / 4;
        cvt_half4<<<(n4 + 255) / 256, 256>>>((const float4*)dec_w, (__half2*)DW, n4);
    }

    // 1) encoded = tanh(seq @ enc_w^T + enc_b)  -> fp16
    {
        dim3 grid(D_K / 128, NTOK / 128);
        mma_gemm<128, 0><<<grid, 256, SM128>>>(S, EW, enc_b, nullptr, E,
                                               D_K, D_IN);
    }
    // 2) logits = encoded @ mem^T  -> fp32
    {
        dim3 grid(1, NTOK / 128);
        mma_gemm<64, 1><<<grid, 256, SM64>>>(E, MEM, nullptr, LG, nullptr,
                                             MSLOTS, D_K);
    }
    // 3) softmax -> att (d_out) + fp16
    softmax_kernel<<<NTOK / 8, 256>>>(LG, att, AT);

    // 4) memory = att @ mem  -> fp32 (d_out) + fp16
    {
        dim3 grid(D_K / 128, NTOK / 128);
        mma_gemm<128, 2><<<grid, 256, SM128>>>(AT, MT, nullptr, memo, M,
                                               D_K, MSLOTS);
    }
    // 5) recon = memory @ dec_w^T + dec_b -> fp32 (d_out)
    {
        dim3 grid(D_IN / 128, NTOK / 128);
        mma_gemm<128, 3><<<grid, 256, SM128>>>(M, DW, dec_b, recon, nullptr,
                                               D_IN, D_K);
    }
}